// round 17
// baseline (speedup 1.0000x reference)
#include <cuda_runtime.h>
#include <cuda_bf16.h>

// Fused DCNv2 forward. Conv runs on tensor cores via mma.sync m16n8k16 bf16
// (sm_80 PTX -> HMMA on sm_103), split-bf16 3-term for fp32-grade accuracy:
//   x = ah+al, w = wh+wl;  x*w ~= ah*wh + ah*wl + al*wh.
// Per warp: D[32px,32oc] = A[32,K96] x B[96,32]. Deform = R13 scalar w/ fast path.

#define HH 512
#define WW 512
#define CC 3
#define OCC 27
#define KK 9
#define HW (HH * WW)

typedef unsigned int       u32;
typedef unsigned long long u64;

struct SmallBlob {
    float wdd[84];        // w_def [o*27 + c*9 + k]
    float boff[28];
    float bdef[4];
};
__constant__ SmallBlob c_s;
__device__   SmallBlob g_scratch;

// Per-lane B fragments for mma m16n8k16 (row.col).
// variant v: 0 = wh k-tile0, 1 = wh k-tile1, 2 = wl k-tile0, 3 = wl k-tile1.
// g_Bfrag[((v*4 + ntile)*32) + lane] = {reg0, reg1} packed as u64 (reg0 = low).
__device__ u64 g_Bfrag[4 * 4 * 32];

__device__ __forceinline__ u32 smem_u32(const void* p) {
    u32 a;
    asm("{ .reg .u64 t; cvta.to.shared.u64 t, %1; cvt.u32.u64 %0, t; }"
        : "=r"(a) : "l"(p));
    return a;
}
// bf16x2 pack: low half = lo
__device__ __forceinline__ u32 bf2(float lo, float hi) {
    u32 r;
    asm("cvt.rn.satfinite.bf16x2.f32 %0, %1, %2;" : "=r"(r) : "f"(hi), "f"(lo));
    return r;
}
#define LDSM_X4(r, addr) \
    asm volatile("ldmatrix.sync.aligned.m8n8.x4.shared.b16 {%0,%1,%2,%3}, [%4];" \
        : "=r"((r)[0]), "=r"((r)[1]), "=r"((r)[2]), "=r"((r)[3]) : "r"(addr))

__device__ __forceinline__ void mma16816(float d[4], const u32 a[4], u32 b0, u32 b1) {
    asm volatile(
        "mma.sync.aligned.m16n8k16.row.col.f32.bf16.bf16.f32 "
        "{%0,%1,%2,%3}, {%4,%5,%6,%7}, {%8,%9}, {%0,%1,%2,%3};"
        : "+f"(d[0]), "+f"(d[1]), "+f"(d[2]), "+f"(d[3])
        : "r"(a[0]), "r"(a[1]), "r"(a[2]), "r"(a[3]), "r"(b0), "r"(b1));
}

__device__ __forceinline__ unsigned short bf16bits(float w) {
    __nv_bfloat16 h = __float2bfloat16(w);
    return *reinterpret_cast<unsigned short*>(&h);
}

__global__ void dcn_prep_kernel(const float* __restrict__ w_off,
                                const float* __restrict__ b_off,
                                const float* __restrict__ w_def,
                                const float* __restrict__ b_def)
{
    const int i = threadIdx.x;
    if (i < 512) {                      // B fragments
        const int lane = i & 31;
        const int nt   = (i >> 5) & 3;
        const int v    = i >> 7;
        const int g    = lane >> 2;
        const int tig  = lane & 3;
        const int kt   = v & 1;
        const int isWl = v >> 1;
        const int col  = nt * 8 + g;    // oc
        const int k0   = kt * 16 + tig * 2;

        unsigned short e[4];
#pragma unroll
        for (int j = 0; j < 4; ++j) {
            const int k = k0 + (j >> 1) * 8 + (j & 1);   // k0, k0+1, k0+8, k0+9
            unsigned short bits = 0;
            if (k < OCC && col < OCC) {
                const float w = w_off[col * 27 + k];
                if (!isWl) bits = bf16bits(w);
                else {
                    __nv_bfloat16 h = __float2bfloat16(w);
                    bits = bf16bits(w - __bfloat162float(h));
                }
            }
            e[j] = bits;
        }
        const u32 r0 = ((u32)e[1] << 16) | e[0];
        const u32 r1 = ((u32)e[3] << 16) | e[2];
        g_Bfrag[i] = ((u64)r1 << 32) | r0;
    } else if (i < 512 + 84) {
        const int j = i - 512;
        g_scratch.wdd[j] = (j < 81) ? w_def[j] : 0.0f;
    } else if (i < 512 + 84 + 28) {
        const int j = i - 596;
        g_scratch.boff[j] = (j < OCC) ? b_off[j] : 0.0f;
    } else if (i < 512 + 84 + 32) {
        const int j = i - 624;
        g_scratch.bdef[j] = (j < 3) ? b_def[j] : 0.0f;
    }
}

// per-warp staging: AH 32 rows x 80B (2560) + AL 2560; D buffer aliases base
// (32 rows x 36 floats = 4608B). Per-warp size 5120B.
#define WSTAGE 5120
#define DPITCH 36

__global__ __launch_bounds__(128)
void dcn_mma_kernel(const float* __restrict__ x, float* __restrict__ out)
{
    __shared__ __align__(16) unsigned char sStage[4 * WSTAGE];

    const int tid  = threadIdx.x;
    const int wid  = tid >> 5;
    const int lane = tid & 31;
    const u32 aBase = smem_u32(sStage) + wid * WSTAGE;

    const int idx = blockIdx.x * 128 + tid;   // pixel id; warp = 32 consecutive px
    const int wI = idx & (WW - 1);
    const int hI = (idx >> 9) & (HH - 1);
    const int b  = idx >> 18;
    const float* xb = x + (size_t)b * CC * HW;

    // ---- 3x3x3 window (zero padded), win[g] ----
    float win[27];
#pragma unroll
    for (int c = 0; c < CC; ++c) {
        const float* xc = xb + c * HW;
#pragma unroll
        for (int ky = 0; ky < 3; ++ky) {
            const int y = hI + ky - 1;
            const bool yv = ((unsigned)y < (unsigned)HH);
#pragma unroll
            for (int kx = 0; kx < 3; ++kx) {
                const int xx = wI + kx - 1;
                const bool v = yv && ((unsigned)xx < (unsigned)WW);
                win[c * 9 + ky * 3 + kx] = v ? __ldg(xc + y * WW + xx) : 0.0f;
            }
        }
    }

    // ---- split-bf16: ah / al packed pairs (16 b32 each, padded) ----
    u32 ahp[16], alp[16];
#pragma unroll
    for (int j = 0; j < 16; ++j) {
        const float flo = (2 * j     < 27) ? win[2 * j]     : 0.0f;
        const float fhi = (2 * j + 1 < 27) ? win[2 * j + 1] : 0.0f;
        const u32 hp = bf2(flo, fhi);
        ahp[j] = hp;
        const float rlo = flo - __uint_as_float(hp << 16);
        const float rhi = fhi - __uint_as_float(hp & 0xffff0000u);
        alp[j] = bf2(rlo, rhi);
    }

    // ---- stage A rows (row = lane), 80B pitch, 4x STS.128 each ----
    {
        unsigned char* rp = sStage + wid * WSTAGE + lane * 80;
        *reinterpret_cast<uint4*>(rp +  0) = make_uint4(ahp[0], ahp[1], ahp[2],  ahp[3]);
        *reinterpret_cast<uint4*>(rp + 16) = make_uint4(ahp[4], ahp[5], ahp[6],  ahp[7]);
        *reinterpret_cast<uint4*>(rp + 32) = make_uint4(ahp[8], ahp[9], ahp[10], ahp[11]);
        *reinterpret_cast<uint4*>(rp + 48) = make_uint4(ahp[12], ahp[13], ahp[14], ahp[15]);
        unsigned char* rq = rp + 2560;
        *reinterpret_cast<uint4*>(rq +  0) = make_uint4(alp[0], alp[1], alp[2],  alp[3]);
        *reinterpret_cast<uint4*>(rq + 16) = make_uint4(alp[4], alp[5], alp[6],  alp[7]);
        *reinterpret_cast<uint4*>(rq + 32) = make_uint4(alp[8], alp[9], alp[10], alp[11]);
        *reinterpret_cast<uint4*>(rq + 48) = make_uint4(alp[12], alp[13], alp[14], alp[15]);
    }
    __syncwarp();

    // ---- ldmatrix A fragments: AH/AL [m][kt][4] ----
    u32 AH[2][2][4], AL[2][2][4];
#pragma unroll
    for (int m = 0; m < 2; ++m)
#pragma unroll
        for (int kt = 0; kt < 2; ++kt) {
            const u32 off = (u32)((m * 16 + (lane & 15)) * 80 + kt * 32 + (lane >> 4) * 16);
            LDSM_X4(AH[m][kt], aBase + off);
            LDSM_X4(AL[m][kt], aBase + 2560 + off);
        }
    __syncwarp();   // staging can be overwritten by D now

    // ---- MMA: D[2 m-tiles][4 n-tiles][4] over 6 K-steps ----
    float d[2][4][4];
#pragma unroll
    for (int m = 0; m < 2; ++m)
#pragma unroll
        for (int nt = 0; nt < 4; ++nt)
#pragma unroll
            for (int q = 0; q < 4; ++q) d[m][nt][q] = 0.0f;

#pragma unroll
    for (int nt = 0; nt < 4; ++nt) {
        u32 b0[4], b1[4];
#pragma unroll
        for (int v = 0; v < 4; ++v) {
            const u64 t = __ldg(&g_Bfrag[(v * 4 + nt) * 32 + lane]);
            b0[v] = (u32)t;
            b1[v] = (u32)(t >> 32);
        }
#pragma unroll
        for (int m = 0; m < 2; ++m) {
            mma16816(d[m][nt], AH[m][0], b0[0], b1[0]);   // ah * wh (k0)
            mma16816(d[m][nt], AH[m][1], b0[1], b1[1]);   // ah * wh (k1)
            mma16816(d[m][nt], AH[m][0], b0[2], b1[2]);   // ah * wl (k0)
            mma16816(d[m][nt], AH[m][1], b0[3], b1[3]);   // ah * wl (k1)
            mma16816(d[m][nt], AL[m][0], b0[0], b1[0]);   // al * wh (k0)
            mma16816(d[m][nt], AL[m][1], b0[1], b1[1]);   // al * wh (k1)
        }
    }

    // ---- D fragments -> shared (pitch 36 floats), then read own row ----
    {
        float* db = reinterpret_cast<float*>(sStage + wid * WSTAGE);
        const int g = lane >> 2, tig = lane & 3;
#pragma unroll
        for (int m = 0; m < 2; ++m)
#pragma unroll
            for (int nt = 0; nt < 4; ++nt) {
                const int col = nt * 8 + tig * 2;
                float* p0 = db + (m * 16 + g) * DPITCH + col;
                p0[0] = d[m][nt][0];  p0[1] = d[m][nt][1];
                float* p1 = p0 + 8 * DPITCH;
                p1[0] = d[m][nt][2];  p1[1] = d[m][nt][3];
            }
    }
    __syncwarp();

    float ow[28];
    {
        const float* dr = reinterpret_cast<const float*>(sStage + wid * WSTAGE)
                        + lane * DPITCH;
#pragma unroll
        for (int j = 0; j < 7; ++j) {
            const float4 q = *reinterpret_cast<const float4*>(dr + 4 * j);
            ow[4 * j + 0] = q.x; ow[4 * j + 1] = q.y;
            ow[4 * j + 2] = q.z; ow[4 * j + 3] = q.w;
        }
    }
#pragma unroll
    for (int oc = 0; oc < OCC; ++oc) ow[oc] += c_s.boff[oc];

    // ---- deformable sampling + 3-channel mix (R13, with interior fast path) ----
    float acc0 = c_s.bdef[0], acc1 = c_s.bdef[1], acc2 = c_s.bdef[2];

#pragma unroll
    for (int k = 0; k < KK; ++k) {
        const float py = (float)hI + (float)(k / 3 - 1) + ow[2 * k];
        const float px = (float)wI + (float)(k % 3 - 1) + ow[2 * k + 1];
        const float m  = __fdividef(1.0f, 1.0f + __expf(-ow[18 + k]));

        const float y0f = floorf(py);
        const float x0f = floorf(px);
        const float dy = py - y0f;
        const float dx = px - x0f;
        const int y0  = (int)y0f;
        const int x0i = (int)x0f;

        const float a  = (1.0f - dy) * m;
        const float bm = dy * m;
        const float w00 = a  * (1.0f - dx);
        const float w01 = a  * dx;
        const float w10 = bm * (1.0f - dx);
        const float w11 = bm * dx;

        const int i00 = y0 * WW + x0i;

        if ((unsigned)y0 < (unsigned)(HH - 1) && (unsigned)x0i < (unsigned)(WW - 1)) {
#pragma unroll
            for (int c = 0; c < CC; ++c) {
                const float* pc = xb + c * HW;
                const float v00 = __ldg(pc + i00);
                const float v01 = __ldg(pc + i00 + 1);
                const float v10 = __ldg(pc + i00 + WW);
                const float v11 = __ldg(pc + i00 + WW + 1);
                const float val = v00 * w00 + v01 * w01 + v10 * w10 + v11 * w11;
                acc0 = fmaf(c_s.wdd[0 * 27 + c * 9 + k], val, acc0);
                acc1 = fmaf(c_s.wdd[1 * 27 + c * 9 + k], val, acc1);
                acc2 = fmaf(c_s.wdd[2 * 27 + c * 9 + k], val, acc2);
            }
        } else {
            const bool y0v = ((unsigned)y0        < (unsigned)HH);
            const bool y1v = ((unsigned)(y0 + 1)  < (unsigned)HH);
            const bool x0v = ((unsigned)x0i       < (unsigned)WW);
            const bool x1v = ((unsigned)(x0i + 1) < (unsigned)WW);
#pragma unroll
            for (int c = 0; c < CC; ++c) {
                const float* pc = xb + c * HW;
                const float v00 = (y0v && x0v) ? __ldg(pc + i00)          : 0.0f;
                const float v01 = (y0v && x1v) ? __ldg(pc + i00 + 1)      : 0.0f;
                const float v10 = (y1v && x0v) ? __ldg(pc + i00 + WW)     : 0.0f;
                const float v11 = (y1v && x1v) ? __ldg(pc + i00 + WW + 1) : 0.0f;
                const float val = v00 * w00 + v01 * w01 + v10 * w10 + v11 * w11;
                acc0 = fmaf(c_s.wdd[0 * 27 + c * 9 + k], val, acc0);
                acc1 = fmaf(c_s.wdd[1 * 27 + c * 9 + k], val, acc1);
                acc2 = fmaf(c_s.wdd[2 * 27 + c * 9 + k], val, acc2);
            }
        }
    }

    const size_t obase = (size_t)b * 3 * HW + (size_t)hI * WW + wI;
    out[obase]          = acc0;
    out[obase + HW]     = acc1;
    out[obase + 2 * HW] = acc2;
}

extern "C" void kernel_launch(void* const* d_in, const int* in_sizes, int n_in,
                              void* d_out, int out_size)
{
    const float* x     = (const float*)d_in[0];
    const float* w_off = (const float*)d_in[1];
    const float* b_off = (const float*)d_in[2];
    const float* w_def = (const float*)d_in[3];
    const float* b_def = (const float*)d_in[4];
    float* out = (float*)d_out;

    // 1) Build B fragments (global) + small blob (scratch).
    dcn_prep_kernel<<<1, 640>>>(w_off, b_off, w_def, b_def);

    // 2) Stage small blob into __constant__.
    void* scratch_ptr = nullptr;
    cudaGetSymbolAddress(&scratch_ptr, g_scratch);
    cudaMemcpyToSymbolAsync(c_s, scratch_ptr, sizeof(SmallBlob), 0,
                            cudaMemcpyDeviceToDevice);

    // 3) Main fused kernel: 1 px/thread, warp = 32 consecutive px.
    const int totalPx = 8 * HW;              // 2,097,152
    dcn_mma_kernel<<<totalPx / 128, 128>>>(x, out);
}